// round 14
// baseline (speedup 1.0000x reference)
#include <cuda_runtime.h>
#include <cuda_bf16.h>

// RepformerLayer: nf=1, nloc=1024, nnei=128, ng2=32, nd=32, nh=4
// One CTA per location i (1024 CTAs, 512 threads = 16 warps, 8 rows/warp).
// R13 = R6/R12 baseline (432us healthy-clock) + two register-neutral deltas:
//   (1) phase-a row remap w*8+r -> QS warp-private -> a->b block barrier becomes
//       __syncwarp (phases a+b fuse into one barrier-free region per head)
//   (2) pre-packed u64 weight tables (16x LDG.64 per phase-a pass)
// Clock canary: HBM >= 40 GB/s = healthy; ~28 GB/s = depressed (judge by ratios).
//
// Algebra:
//   S_h    = g2 @ M_h @ g2^T,      M_h = Wq_h Wk_h^T / sqrt(nd)   (precomputed)
//   g2_out = b_head + sum_h A_h @ P_h,  P_h = g2 @ W2_h,  W2_h = w_v_h @ w_head_h
//   h2_out = (sum_h weq[h] * A_h) @ h2   (ASUM in smem)

#define NLOC 1024
#define NNEI 128
#define NG2  32
#define NH   4

#define INV_SQRT_ND 0.17677669529663687f   // 1/sqrt(32)
#define INV_SQRT3   0.57735026918962576f   // 1/sqrt(3)
#define ATTNW_SHIFT 20.0f

typedef unsigned long long u64;

__device__ __forceinline__ u64 pk2(float lo, float hi) {
    u64 r;
    asm("mov.b64 %0, {%1, %2};" : "=l"(r) : "f"(lo), "f"(hi));
    return r;
}
__device__ __forceinline__ void upk2(u64 v, float& lo, float& hi) {
    asm("mov.b64 {%0, %1}, %2;" : "=f"(lo), "=f"(hi) : "l"(v));
}
__device__ __forceinline__ void fma2(u64& d, u64 a, u64 b) {
    asm("fma.rn.f32x2 %0, %1, %2, %0;" : "+l"(d) : "l"(a), "l"(b));
}
__device__ __forceinline__ float hsum2(u64 v) {
    float lo, hi; upk2(v, lo, hi); return lo + hi;
}

// Pre-packed weight tables: element [h][t][o] packs rows (2t, 2t+1) as f32x2.
//   W2[h][j][o] = sum_g w_v[j, g*4+h] * w_head[g*4+h, o]
//   M [h][j][o] = (1/sqrt(nd)) * sum_d w_qk[j, d*8+h] * w_qk[o, d*8+4+h]
__device__ u64 g_W2p[NH][16][NG2];
__device__ u64 g_Mp[NH][16][NG2];

__global__ void precompute_kernel(const float* __restrict__ w_v,
                                  const float* __restrict__ w_head,
                                  const float* __restrict__ w_qk) {
    int t = blockIdx.x * blockDim.x + threadIdx.x;   // 4096 outputs (u64)
    if (t >= 2 * NH * 16 * NG2) return;
    int o  = t & 31;
    int tp = (t >> 5) & 15;
    int h  = (t >> 9) & 3;
    if (t < NH * 16 * NG2) {
        float s0 = 0.0f, s1 = 0.0f;
#pragma unroll
        for (int g = 0; g < 32; g++) {
            float wh = w_head[(g * 4 + h) * 32 + o];
            s0 = fmaf(w_v[(2 * tp) * 128 + g * 4 + h], wh, s0);
            s1 = fmaf(w_v[(2 * tp + 1) * 128 + g * 4 + h], wh, s1);
        }
        g_W2p[h][tp][o] = pk2(s0, s1);
    } else {
        float s0 = 0.0f, s1 = 0.0f;
#pragma unroll
        for (int d = 0; d < 32; d++) {
            float wk = w_qk[o * 256 + d * 8 + 4 + h];
            s0 = fmaf(w_qk[(2 * tp) * 256 + d * 8 + h], wk, s0);
            s1 = fmaf(w_qk[(2 * tp + 1) * 256 + d * 8 + h], wk, s1);
        }
        g_Mp[h][tp][o] = pk2(s0 * INV_SQRT_ND, s1 * INV_SQRT_ND);
    }
}

// ---- shared memory layout (floats) ----
// G2P  [128][36]    : 0      .. 4608    (pad 36: conflict-free .128 row reads)
// QS   [128][36]    : 4608   .. 9216    (warp-private: warp w owns rows 8w..8w+7)
// PS   [32][4][40]  : 9216   .. 14336   (PS[k][o] at (k%32)*160 + (k/32)*40 + o)
// AS   [128][144]   : 14336  .. 32768   (A[q][k] at q*144 + (k/32)*36 + (k%32))
// ASUM [128][132]   : 32768  .. 49664
// H2S  [128][5]     : 49664  .. 50304
// SWS  [128]        : 50304  .. 50432
// MFS  [128]        : 50432  .. 50560
#define SM_FLOATS 50560

__global__ __launch_bounds__(512, 1)
void repformer_kernel(const float* __restrict__ g2,
                      const float* __restrict__ h2,
                      const float* __restrict__ sw,
                      const float* __restrict__ b_head,
                      const float* __restrict__ w_eqhead,
                      const int*   __restrict__ nlist_mask,
                      float* __restrict__ out) {
    extern __shared__ float sm[];
    float* G2P  = sm;
    float* QS   = sm + 4608;
    float* PS   = sm + 9216;
    float* AS   = sm + 14336;
    float* ASUM = sm + 32768;
    float* H2S  = sm + 49664;
    float* SWS  = sm + 50304;
    float* MFS  = sm + 50432;

    const int i    = blockIdx.x;
    const int tid  = threadIdx.x;
    const int lane = tid & 31;
    const int w    = tid >> 5;   // warp 0..15
    const int g    = lane >> 3;  // phase-c k-quarter group
    const int s    = lane & 7;

    // ---- load tile ----
    {
        const float4* src = (const float4*)(g2 + (size_t)i * NNEI * NG2);
        for (int v = tid; v < NNEI * NG2 / 4; v += 512) {
            int n  = v >> 3;
            int j4 = v & 7;
            *(float4*)(G2P + n * 36 + j4 * 4) = src[v];
        }
        if (tid < NNEI) {
            int n = tid;
            size_t base = ((size_t)i * NNEI + n);
            H2S[n * 5 + 0] = h2[base * 3 + 0];
            H2S[n * 5 + 1] = h2[base * 3 + 1];
            H2S[n * 5 + 2] = h2[base * 3 + 2];
            SWS[n] = sw[base];
            MFS[n] = nlist_mask[base] ? 1.0f : 0.0f;
        }
    }
    __syncthreads();

    // phase-c persistent accumulators: warp w owns rows w*8..+7;
    // lane (g,s) owns o in {s,s+8} (accO0) and {s+16,s+24} (accO1), k in [g*32, g*32+32)
    u64 accO0[8], accO1[8];
#pragma unroll
    for (int r = 0; r < 8; r++) { accO0[r] = 0ull; accO1[r] = 0ull; }

#pragma unroll 1
    for (int h = 0; h < NH; h++) {
        const float weq = w_eqhead[h];

        // ============ phase a: QS = g2 @ M_h,  PS = g2 @ W2_h ============
        // thread: column = lane, rows = w*8 + r (r=0..7) — QS rows are the SAME
        // rows this warp consumes in phase b (warp-private QS, no block barrier).
#pragma unroll 1
        for (int m = 0; m < 2; m++) {
            u64 wreg[16];
            if (m == 0) {
#pragma unroll
                for (int t = 0; t < 16; t++) wreg[t] = g_Mp[h][t][lane];
            } else {
#pragma unroll
                for (int t = 0; t < 16; t++) wreg[t] = g_W2p[h][t][lane];
            }
            u64 acc[8];
#pragma unroll
            for (int r = 0; r < 8; r++) acc[r] = 0ull;
#pragma unroll
            for (int j4 = 0; j4 < 8; j4++) {
#pragma unroll
                for (int r = 0; r < 8; r++) {
                    ulonglong2 gv = *(const ulonglong2*)(G2P + (w * 8 + r) * 36 + j4 * 4);
                    fma2(acc[r], gv.x, wreg[2 * j4]);
                    fma2(acc[r], gv.y, wreg[2 * j4 + 1]);
                }
            }
            if (m == 0) {
#pragma unroll
                for (int r = 0; r < 8; r++)
                    QS[(w * 8 + r) * 36 + lane] = hsum2(acc[r]);
            } else {
#pragma unroll
                for (int r = 0; r < 8; r++) {
                    int row = w * 8 + r;
                    PS[(row & 31) * 160 + (row >> 5) * 40 + lane] = hsum2(acc[r]);
                }
            }
        }
        __syncwarp();   // QS warp-private: cross-lane STS->LDS visibility only

        // ============ phase b: S = T @ g2^T + scaling + softmax + masking ============
        // warp w owns rows w*8..w*8+7; lane owns k = lane + 32*m (K operand = G2P rows)
        {
            const int qbase = w * 8;

            float hk0[4], hk1[4], hk2[4], swk[4], kc[4];
#pragma unroll
            for (int m = 0; m < 4; m++) {
                int k = lane + 32 * m;
                hk0[m] = H2S[k * 5 + 0];
                hk1[m] = H2S[k * 5 + 1];
                hk2[m] = H2S[k * 5 + 2];
                swk[m] = SWS[k];
                kc[m]  = swk[m] * MFS[k];
            }

            // packed accumulators: pair 0 = (m0,m1), pair 1 = (m2,m3)
            u64 acc2[8][2];
#pragma unroll
            for (int r = 0; r < 8; r++) { acc2[r][0] = 0ull; acc2[r][1] = 0ull; }

#pragma unroll
            for (int d4 = 0; d4 < 8; d4++) {
                float4 kv[4];
#pragma unroll
                for (int m = 0; m < 4; m++)
                    kv[m] = *(const float4*)(G2P + (lane + 32 * m) * 36 + d4 * 4);
                u64 kp0x = pk2(kv[0].x, kv[1].x), kp1x = pk2(kv[2].x, kv[3].x);
                u64 kp0y = pk2(kv[0].y, kv[1].y), kp1y = pk2(kv[2].y, kv[3].y);
                u64 kp0z = pk2(kv[0].z, kv[1].z), kp1z = pk2(kv[2].z, kv[3].z);
                u64 kp0w = pk2(kv[0].w, kv[1].w), kp1w = pk2(kv[2].w, kv[3].w);
#pragma unroll
                for (int r = 0; r < 8; r++) {
                    float4 qv = *(const float4*)(QS + (qbase + r) * 36 + d4 * 4);
                    u64 qx = pk2(qv.x, qv.x);
                    u64 qy = pk2(qv.y, qv.y);
                    u64 qz = pk2(qv.z, qv.z);
                    u64 qw = pk2(qv.w, qv.w);
                    fma2(acc2[r][0], qx, kp0x); fma2(acc2[r][1], qx, kp1x);
                    fma2(acc2[r][0], qy, kp0y); fma2(acc2[r][1], qy, kp1y);
                    fma2(acc2[r][0], qz, kp0z); fma2(acc2[r][1], qz, kp1z);
                    fma2(acc2[r][0], qw, kp0w); fma2(acc2[r][1], qw, kp1w);
                }
            }

#pragma unroll
            for (int r = 0; r < 8; r++) {
                const int q = qbase + r;
                const float hq0 = H2S[q * 5 + 0];
                const float hq1 = H2S[q * 5 + 1];
                const float hq2 = H2S[q * 5 + 2];
                const float swq = SWS[q];
                const float mq  = MFS[q];

                float sc[4];
                upk2(acc2[r][0], sc[0], sc[1]);
                upk2(acc2[r][1], sc[2], sc[3]);

                float hh[4], val[4];
#pragma unroll
                for (int m = 0; m < 4; m++) {
                    hh[m] = fmaf(hq0, hk0[m], fmaf(hq1, hk1[m], hq2 * hk2[m]));
                    float a = sc[m] * hh[m];
                    val[m] = (a + ATTNW_SHIFT) * swq * swk[m] - ATTNW_SHIFT;
                }
                float mx = fmaxf(fmaxf(val[0], val[1]), fmaxf(val[2], val[3]));
#pragma unroll
                for (int sh = 16; sh > 0; sh >>= 1)
                    mx = fmaxf(mx, __shfl_xor_sync(0xffffffffu, mx, sh));
                float ssum = 0.0f;
#pragma unroll
                for (int m = 0; m < 4; m++) {
                    val[m] = __expf(val[m] - mx);
                    ssum += val[m];
                }
#pragma unroll
                for (int sh = 16; sh > 0; sh >>= 1)
                    ssum += __shfl_xor_sync(0xffffffffu, ssum, sh);
                const float rowc = __frcp_rn(ssum) * swq * mq * INV_SQRT3;

#pragma unroll
                for (int m = 0; m < 4; m++) {
                    float A = val[m] * rowc * kc[m] * hh[m];
                    // AS layout: q*144 + (k/32)*36 + (k%32), k = lane + 32m
                    AS[q * 144 + m * 36 + lane] = A;
                    int kk = lane + 32 * m;
                    if (h == 0) ASUM[q * 132 + kk] = weq * A;
                    else        ASUM[q * 132 + kk] += weq * A;
                }
            }
        }
        __syncthreads();   // orders: all warps' PS writes (phase a) -> phase-c reads;
                           // also AS STS->LDS (warp-private) visibility

        // ============ phase c: accO += A[q][k-quarter] * P[k][o-set] (grouped gather) ======
        {
            const int rowbase = w * 8;
            const float* PSg = PS + g * 40;
#pragma unroll 2
            for (int k4 = 0; k4 < 8; k4++) {
                // P operands, row-invariant: k = g*32 + k4*4 + j
                u64 pP0[4], pP1[4];
#pragma unroll
                for (int j = 0; j < 4; j++) {
                    const float* prow = PSg + (k4 * 4 + j) * 160;
                    pP0[j] = pk2(prow[s],      prow[s + 8]);
                    pP1[j] = pk2(prow[s + 16], prow[s + 24]);
                }
#pragma unroll
                for (int r = 0; r < 8; r++) {
                    // one LDS.128 serves 4 groups' distinct 16B chunks
                    const float4 a = *(const float4*)(AS + (rowbase + r) * 144 + g * 36 + k4 * 4);
                    u64 a0 = pk2(a.x, a.x);
                    u64 a1 = pk2(a.y, a.y);
                    u64 a2 = pk2(a.z, a.z);
                    u64 a3 = pk2(a.w, a.w);
                    fma2(accO0[r], a0, pP0[0]); fma2(accO1[r], a0, pP1[0]);
                    fma2(accO0[r], a1, pP0[1]); fma2(accO1[r], a1, pP1[1]);
                    fma2(accO0[r], a2, pP0[2]); fma2(accO1[r], a2, pP1[2]);
                    fma2(accO0[r], a3, pP0[3]); fma2(accO1[r], a3, pP1[3]);
                }
            }
        }
        __syncthreads();   // all warps done reading PS before next head overwrites
    }

    // ---- epilogue: g2_out — bfly-reduce partials over k-quarter groups ----
    {
        const int rowbase = w * 8;
        const float bb0 = b_head[s];
        const float bb1 = b_head[s + 8];
        const float bb2 = b_head[s + 16];
        const float bb3 = b_head[s + 24];
#pragma unroll
        for (int r = 0; r < 8; r++) {
            float o0, o1, o2, o3;
            upk2(accO0[r], o0, o1);
            upk2(accO1[r], o2, o3);
#pragma unroll
            for (int sh = 8; sh <= 16; sh <<= 1) {
                o0 += __shfl_xor_sync(0xffffffffu, o0, sh);
                o1 += __shfl_xor_sync(0xffffffffu, o1, sh);
                o2 += __shfl_xor_sync(0xffffffffu, o2, sh);
                o3 += __shfl_xor_sync(0xffffffffu, o3, sh);
            }
            if (g == 0) {
                int q = rowbase + r;
                float* po = out + ((size_t)i * NNEI + q) * 32;
                po[s]      = o0 + bb0;
                po[s + 8]  = o1 + bb1;
                po[s + 16] = o2 + bb2;
                po[s + 24] = o3 + bb3;
            }
        }
    }

    // ---- epilogue: h2_out = ASUM @ h2 ----
    if (tid < 128) {
        const int q = tid;
        float s0 = 0.0f, s1 = 0.0f, s2 = 0.0f;
#pragma unroll 4
        for (int k4 = 0; k4 < 32; k4++) {
            float4 a = *(const float4*)(ASUM + q * 132 + k4 * 4);
            float av[4] = {a.x, a.y, a.z, a.w};
#pragma unroll
            for (int u = 0; u < 4; u++) {
                int k = k4 * 4 + u;
                s0 = fmaf(av[u], H2S[k * 5 + 0], s0);
                s1 = fmaf(av[u], H2S[k * 5 + 1], s1);
                s2 = fmaf(av[u], H2S[k * 5 + 2], s2);
            }
        }
        float* oh = out + (size_t)NLOC * NNEI * 32;
        size_t base = ((size_t)i * NNEI + q) * 3;
        oh[base + 0] = s0;
        oh[base + 1] = s1;
        oh[base + 2] = s2;
    }
}

extern "C" void kernel_launch(void* const* d_in, const int* in_sizes, int n_in,
                              void* d_out, int out_size) {
    const float* g2       = (const float*)d_in[0];
    const float* h2       = (const float*)d_in[1];
    const float* sw       = (const float*)d_in[2];
    const float* w_qk     = (const float*)d_in[3];
    const float* w_v      = (const float*)d_in[4];
    const float* w_head   = (const float*)d_in[5];
    const float* b_head   = (const float*)d_in[6];
    const float* w_eqhead = (const float*)d_in[7];
    const int*   nmask    = (const int*)d_in[8];
    float* out = (float*)d_out;

    precompute_kernel<<<16, 256>>>(w_v, w_head, w_qk);

    const size_t smem = (size_t)SM_FLOATS * sizeof(float);   // ~197.5 KB
    cudaFuncSetAttribute(repformer_kernel,
                         cudaFuncAttributeMaxDynamicSharedMemorySize, (int)smem);
    repformer_kernel<<<NLOC, 512, smem>>>(g2, h2, sw, b_head, w_eqhead, nmask, out);
}

// round 16
// speedup vs baseline: 1.0566x; 1.0566x over previous
#include <cuda_runtime.h>
#include <cuda_bf16.h>

// RepformerLayer: nf=1, nloc=1024, nnei=128, ng2=32, nd=32, nh=4
// One CTA per location i (1024 CTAs, 512 threads = 16 warps, 8 rows/warp).
// R15 = R12 VERBATIM (432us baseline) + softmax row-max via redux.sync.max.s32
//       on the monotone float<->int mapping (redux.f32 is NOT supported on
//       sm_103 — R14 compile fail). 1 REDUX + 4 ALU replaces 5 SHFL + 5 FMNMX
//       per row and collapses the 5-deep shuffle latency chain.
//
// Algebra:
//   S_h    = g2 @ M_h @ g2^T,      M_h = Wq_h Wk_h^T / sqrt(nd)   (precomputed)
//   g2_out = b_head + sum_h A_h @ P_h,  P_h = g2 @ W2_h,  W2_h = w_v_h @ w_head_h
//   h2_out = (sum_h weq[h] * A_h) @ h2   (ASUM in smem)

#define NLOC 1024
#define NNEI 128
#define NG2  32
#define NH   4

#define INV_SQRT_ND 0.17677669529663687f   // 1/sqrt(32)
#define INV_SQRT3   0.57735026918962576f   // 1/sqrt(3)
#define ATTNW_SHIFT 20.0f

typedef unsigned long long u64;

__device__ __forceinline__ u64 pk2(float lo, float hi) {
    u64 r;
    asm("mov.b64 %0, {%1, %2};" : "=l"(r) : "f"(lo), "f"(hi));
    return r;
}
__device__ __forceinline__ void upk2(u64 v, float& lo, float& hi) {
    asm("mov.b64 {%0, %1}, %2;" : "=f"(lo), "=f"(hi) : "l"(v));
}
__device__ __forceinline__ void fma2(u64& d, u64 a, u64 b) {
    asm("fma.rn.f32x2 %0, %1, %2, %0;" : "+l"(d) : "l"(a), "l"(b));
}
__device__ __forceinline__ float hsum2(u64 v) {
    float lo, hi; upk2(v, lo, hi); return lo + hi;
}
// Warp-wide f32 max via s32 redux (sm_80+) on the monotone float<->int map:
// non-negative floats compare correctly as s32; negatives get order-flipped by
// xor 0x7fffffff. Map is self-inverse, max is exact (order-preserving).
__device__ __forceinline__ float warp_max_f32(float v) {
    int iv = __float_as_int(v);
    iv = (iv >= 0) ? iv : (iv ^ 0x7fffffff);
    int r;
    asm("redux.sync.max.s32 %0, %1, 0xffffffff;" : "=r"(r) : "r"(iv));
    r = (r >= 0) ? r : (r ^ 0x7fffffff);
    return __int_as_float(r);
}

// Precomputed W2[h][j][o] = sum_g w_v[j, g*4+h] * w_head[g*4+h, o]
// Precomputed M[h][j][jp] = (1/sqrt(nd)) * sum_d w_qk[j, d*8+h] * w_qk[jp, d*8+4+h]
__device__ float g_W2[NH][NG2][NG2];
__device__ float g_M[NH][NG2][NG2];

__global__ void precompute_kernel(const float* __restrict__ w_v,
                                  const float* __restrict__ w_head,
                                  const float* __restrict__ w_qk) {
    int t = blockIdx.x * blockDim.x + threadIdx.x;   // 8192 outputs
    if (t >= 2 * NH * NG2 * NG2) return;
    int o = t & 31;
    int j = (t >> 5) & 31;
    int h = (t >> 10) & 3;
    if (t < NH * NG2 * NG2) {
        float s = 0.0f;
#pragma unroll
        for (int g = 0; g < 32; g++)
            s = fmaf(w_v[j * 128 + g * 4 + h], w_head[(g * 4 + h) * 32 + o], s);
        g_W2[h][j][o] = s;
    } else {
        float s = 0.0f;
#pragma unroll
        for (int d = 0; d < 32; d++)
            s = fmaf(w_qk[j * 256 + d * 8 + h], w_qk[o * 256 + d * 8 + 4 + h], s);
        g_M[h][j][o] = s * INV_SQRT_ND;
    }
}

// ---- shared memory layout (floats) ----
// G2P  [128][36]    : 0      .. 4608    (pad 36: conflict-free .128 row reads)
// QS   [128][36]    : 4608   .. 9216
// PS   [32][4][40]  : 9216   .. 14336   (PS[k][o] at (k%32)*160 + (k/32)*40 + o)
// AS   [128][144]   : 14336  .. 32768   (A[q][k] at q*144 + (k/32)*36 + (k%32))
// ASUM [128][132]   : 32768  .. 49664
// H2S  [128][5]     : 49664  .. 50304
// SWS  [128]        : 50304  .. 50432
// MFS  [128]        : 50432  .. 50560
#define SM_FLOATS 50560

__global__ __launch_bounds__(512, 1)
void repformer_kernel(const float* __restrict__ g2,
                      const float* __restrict__ h2,
                      const float* __restrict__ sw,
                      const float* __restrict__ b_head,
                      const float* __restrict__ w_eqhead,
                      const int*   __restrict__ nlist_mask,
                      float* __restrict__ out) {
    extern __shared__ float sm[];
    float* G2P  = sm;
    float* QS   = sm + 4608;
    float* PS   = sm + 9216;
    float* AS   = sm + 14336;
    float* ASUM = sm + 32768;
    float* H2S  = sm + 49664;
    float* SWS  = sm + 50304;
    float* MFS  = sm + 50432;

    const int i    = blockIdx.x;
    const int tid  = threadIdx.x;
    const int lane = tid & 31;
    const int w    = tid >> 5;   // warp 0..15
    const int g    = lane >> 3;  // phase-c k-quarter group
    const int s    = lane & 7;

    // ---- load tile ----
    {
        const float4* src = (const float4*)(g2 + (size_t)i * NNEI * NG2);
        for (int v = tid; v < NNEI * NG2 / 4; v += 512) {
            int n  = v >> 3;
            int j4 = v & 7;
            *(float4*)(G2P + n * 36 + j4 * 4) = src[v];
        }
        if (tid < NNEI) {
            int n = tid;
            size_t base = ((size_t)i * NNEI + n);
            H2S[n * 5 + 0] = h2[base * 3 + 0];
            H2S[n * 5 + 1] = h2[base * 3 + 1];
            H2S[n * 5 + 2] = h2[base * 3 + 2];
            SWS[n] = sw[base];
            MFS[n] = nlist_mask[base] ? 1.0f : 0.0f;
        }
    }
    __syncthreads();

    // phase-c persistent accumulators: warp w owns rows w*8..+7;
    // lane (g,s) owns o in {s,s+8} (accO0) and {s+16,s+24} (accO1), k in [g*32, g*32+32)
    u64 accO0[8], accO1[8];
#pragma unroll
    for (int r = 0; r < 8; r++) { accO0[r] = 0ull; accO1[r] = 0ull; }

#pragma unroll 1
    for (int h = 0; h < NH; h++) {
        const float weq = w_eqhead[h];

        // ============ phase a: QS = g2 @ M_h,  PS = g2 @ W2_h ============
        // thread: column = lane, rows = w + 16*r (r=0..7). Packed weights + FFMA2.
#pragma unroll 1
        for (int m = 0; m < 2; m++) {
            u64 wreg[16];
            if (m == 0) {
#pragma unroll
                for (int t = 0; t < 16; t++)
                    wreg[t] = pk2(g_M[h][2 * t][lane], g_M[h][2 * t + 1][lane]);
            } else {
#pragma unroll
                for (int t = 0; t < 16; t++)
                    wreg[t] = pk2(g_W2[h][2 * t][lane], g_W2[h][2 * t + 1][lane]);
            }
            u64 acc[8];
#pragma unroll
            for (int r = 0; r < 8; r++) acc[r] = 0ull;
#pragma unroll
            for (int j4 = 0; j4 < 8; j4++) {
#pragma unroll
                for (int r = 0; r < 8; r++) {
                    ulonglong2 gv = *(const ulonglong2*)(G2P + (w + 16 * r) * 36 + j4 * 4);
                    fma2(acc[r], gv.x, wreg[2 * j4]);
                    fma2(acc[r], gv.y, wreg[2 * j4 + 1]);
                }
            }
            if (m == 0) {
#pragma unroll
                for (int r = 0; r < 8; r++)
                    QS[(w + 16 * r) * 36 + lane] = hsum2(acc[r]);
            } else {
#pragma unroll
                for (int r = 0; r < 8; r++) {
                    int row = w + 16 * r;
                    PS[(row & 31) * 160 + (row >> 5) * 40 + lane] = hsum2(acc[r]);
                }
            }
        }
        __syncthreads();

        // ============ phase b: S = T @ g2^T + scaling + softmax + masking ============
        // warp w owns rows w*8..w*8+7; lane owns k = lane + 32*m (K operand = G2P rows)
        {
            const int qbase = w * 8;

            float hk0[4], hk1[4], hk2[4], swk[4], kc[4];
#pragma unroll
            for (int m = 0; m < 4; m++) {
                int k = lane + 32 * m;
                hk0[m] = H2S[k * 5 + 0];
                hk1[m] = H2S[k * 5 + 1];
                hk2[m] = H2S[k * 5 + 2];
                swk[m] = SWS[k];
                kc[m]  = swk[m] * MFS[k];
            }

            // packed accumulators: pair 0 = (m0,m1), pair 1 = (m2,m3)
            u64 acc2[8][2];
#pragma unroll
            for (int r = 0; r < 8; r++) { acc2[r][0] = 0ull; acc2[r][1] = 0ull; }

#pragma unroll
            for (int d4 = 0; d4 < 8; d4++) {
                float4 kv[4];
#pragma unroll
                for (int m = 0; m < 4; m++)
                    kv[m] = *(const float4*)(G2P + (lane + 32 * m) * 36 + d4 * 4);
                u64 kp0x = pk2(kv[0].x, kv[1].x), kp1x = pk2(kv[2].x, kv[3].x);
                u64 kp0y = pk2(kv[0].y, kv[1].y), kp1y = pk2(kv[2].y, kv[3].y);
                u64 kp0z = pk2(kv[0].z, kv[1].z), kp1z = pk2(kv[2].z, kv[3].z);
                u64 kp0w = pk2(kv[0].w, kv[1].w), kp1w = pk2(kv[2].w, kv[3].w);
#pragma unroll
                for (int r = 0; r < 8; r++) {
                    float4 qv = *(const float4*)(QS + (qbase + r) * 36 + d4 * 4);
                    u64 qx = pk2(qv.x, qv.x);
                    u64 qy = pk2(qv.y, qv.y);
                    u64 qz = pk2(qv.z, qv.z);
                    u64 qw = pk2(qv.w, qv.w);
                    fma2(acc2[r][0], qx, kp0x); fma2(acc2[r][1], qx, kp1x);
                    fma2(acc2[r][0], qy, kp0y); fma2(acc2[r][1], qy, kp1y);
                    fma2(acc2[r][0], qz, kp0z); fma2(acc2[r][1], qz, kp1z);
                    fma2(acc2[r][0], qw, kp0w); fma2(acc2[r][1], qw, kp1w);
                }
            }

#pragma unroll
            for (int r = 0; r < 8; r++) {
                const int q = qbase + r;
                const float hq0 = H2S[q * 5 + 0];
                const float hq1 = H2S[q * 5 + 1];
                const float hq2 = H2S[q * 5 + 2];
                const float swq = SWS[q];
                const float mq  = MFS[q];

                float sc[4];
                upk2(acc2[r][0], sc[0], sc[1]);
                upk2(acc2[r][1], sc[2], sc[3]);

                float hh[4], val[4];
#pragma unroll
                for (int m = 0; m < 4; m++) {
                    hh[m] = fmaf(hq0, hk0[m], fmaf(hq1, hk1[m], hq2 * hk2[m]));
                    float a = sc[m] * hh[m];
                    val[m] = (a + ATTNW_SHIFT) * swq * swk[m] - ATTNW_SHIFT;
                }
                // row max: single REDUX via monotone float<->s32 map (exact)
                float mx = fmaxf(fmaxf(val[0], val[1]), fmaxf(val[2], val[3]));
                mx = warp_max_f32(mx);
                float ssum = 0.0f;
#pragma unroll
                for (int m = 0; m < 4; m++) {
                    val[m] = __expf(val[m] - mx);
                    ssum += val[m];
                }
#pragma unroll
                for (int sh = 16; sh > 0; sh >>= 1)
                    ssum += __shfl_xor_sync(0xffffffffu, ssum, sh);
                const float rowc = __frcp_rn(ssum) * swq * mq * INV_SQRT3;

#pragma unroll
                for (int m = 0; m < 4; m++) {
                    float A = val[m] * rowc * kc[m] * hh[m];
                    // AS layout: q*144 + (k/32)*36 + (k%32), k = lane + 32m
                    AS[q * 144 + m * 36 + lane] = A;
                    int kk = lane + 32 * m;
                    if (h == 0) ASUM[q * 132 + kk] = weq * A;
                    else        ASUM[q * 132 + kk] += weq * A;
                }
            }
        }
        __syncwarp();   // AS warp-private: only STS->LDS visibility within warp needed

        // ============ phase c: accO += A[q][k-quarter] * P[k][o-set] (grouped gather) ======
        {
            const int rowbase = w * 8;
            const float* PSg = PS + g * 40;
#pragma unroll 2
            for (int k4 = 0; k4 < 8; k4++) {
                // P operands, row-invariant: k = g*32 + k4*4 + j
                u64 pP0[4], pP1[4];
#pragma unroll
                for (int j = 0; j < 4; j++) {
                    const float* prow = PSg + (k4 * 4 + j) * 160;
                    pP0[j] = pk2(prow[s],      prow[s + 8]);
                    pP1[j] = pk2(prow[s + 16], prow[s + 24]);
                }
#pragma unroll
                for (int r = 0; r < 8; r++) {
                    // one LDS.128 serves 4 groups' distinct 16B chunks
                    const float4 a = *(const float4*)(AS + (rowbase + r) * 144 + g * 36 + k4 * 4);
                    u64 a0 = pk2(a.x, a.x);
                    u64 a1 = pk2(a.y, a.y);
                    u64 a2 = pk2(a.z, a.z);
                    u64 a3 = pk2(a.w, a.w);
                    fma2(accO0[r], a0, pP0[0]); fma2(accO1[r], a0, pP1[0]);
                    fma2(accO0[r], a1, pP0[1]); fma2(accO1[r], a1, pP1[1]);
                    fma2(accO0[r], a2, pP0[2]); fma2(accO1[r], a2, pP1[2]);
                    fma2(accO0[r], a3, pP0[3]); fma2(accO1[r], a3, pP1[3]);
                }
            }
        }
        __syncthreads();   // QS/PS reused next head
    }

    // ---- epilogue: g2_out — bfly-reduce partials over k-quarter groups ----
    {
        const int rowbase = w * 8;
        const float bb0 = b_head[s];
        const float bb1 = b_head[s + 8];
        const float bb2 = b_head[s + 16];
        const float bb3 = b_head[s + 24];
#pragma unroll
        for (int r = 0; r < 8; r++) {
            float o0, o1, o2, o3;
            upk2(accO0[r], o0, o1);
            upk2(accO1[r], o2, o3);
#pragma unroll
            for (int sh = 8; sh <= 16; sh <<= 1) {
                o0 += __shfl_xor_sync(0xffffffffu, o0, sh);
                o1 += __shfl_xor_sync(0xffffffffu, o1, sh);
                o2 += __shfl_xor_sync(0xffffffffu, o2, sh);
                o3 += __shfl_xor_sync(0xffffffffu, o3, sh);
            }
            if (g == 0) {
                int q = rowbase + r;
                float* po = out + ((size_t)i * NNEI + q) * 32;
                po[s]      = o0 + bb0;
                po[s + 8]  = o1 + bb1;
                po[s + 16] = o2 + bb2;
                po[s + 24] = o3 + bb3;
            }
        }
    }

    // ---- epilogue: h2_out = ASUM @ h2 ----
    if (tid < 128) {
        const int q = tid;
        float s0 = 0.0f, s1 = 0.0f, s2 = 0.0f;
#pragma unroll 4
        for (int k4 = 0; k4 < 32; k4++) {
            float4 a = *(const float4*)(ASUM + q * 132 + k4 * 4);
            float av[4] = {a.x, a.y, a.z, a.w};
#pragma unroll
            for (int u = 0; u < 4; u++) {
                int k = k4 * 4 + u;
                s0 = fmaf(av[u], H2S[k * 5 + 0], s0);
                s1 = fmaf(av[u], H2S[k * 5 + 1], s1);
                s2 = fmaf(av[u], H2S[k * 5 + 2], s2);
            }
        }
        float* oh = out + (size_t)NLOC * NNEI * 32;
        size_t base = ((size_t)i * NNEI + q) * 3;
        oh[base + 0] = s0;
        oh[base + 1] = s1;
        oh[base + 2] = s2;
    }
}

extern "C" void kernel_launch(void* const* d_in, const int* in_sizes, int n_in,
                              void* d_out, int out_size) {
    const float* g2       = (const float*)d_in[0];
    const float* h2       = (const float*)d_in[1];
    const float* sw       = (const float*)d_in[2];
    const float* w_qk     = (const float*)d_in[3];
    const float* w_v      = (const float*)d_in[4];
    const float* w_head   = (const float*)d_in[5];
    const float* b_head   = (const float*)d_in[6];
    const float* w_eqhead = (const float*)d_in[7];
    const int*   nmask    = (const int*)d_in[8];
    float* out = (float*)d_out;

    precompute_kernel<<<32, 256>>>(w_v, w_head, w_qk);

    const size_t smem = (size_t)SM_FLOATS * sizeof(float);   // ~197.5 KB
    cudaFuncSetAttribute(repformer_kernel,
                         cudaFuncAttributeMaxDynamicSharedMemorySize, (int)smem);
    repformer_kernel<<<NLOC, 512, smem>>>(g2, h2, sw, b_head, w_eqhead, nmask, out);
}

// round 17
// speedup vs baseline: 1.0841x; 1.0260x over previous
#include <cuda_runtime.h>
#include <cuda_bf16.h>

// RepformerLayer: nf=1, nloc=1024, nnei=128, ng2=32, nd=32, nh=4
// One CTA per location i (1024 CTAs, 512 threads = 16 warps, 8 rows/warp).
// R16 = R15 (424.5us: R12 + redux row-max) + fixed-point redux row-SUM:
//       ssum via redux.sync.add.s32 on 2^23-scaled values. Post-max-sub the row
//       max exp is 1.0 -> per-lane partial <= 4, ssum in [1,128]; scale 2^23
//       keeps the 32-lane int sum <= 2^30 (no overflow), quantization rel err
//       <= 2e-6 on the normalization (gate is 1e-3). Replaces the remaining
//       5xSHFL+5xFADD chain per softmax row.
//
// Algebra:
//   S_h    = g2 @ M_h @ g2^T,      M_h = Wq_h Wk_h^T / sqrt(nd)   (precomputed)
//   g2_out = b_head + sum_h A_h @ P_h,  P_h = g2 @ W2_h,  W2_h = w_v_h @ w_head_h
//   h2_out = (sum_h weq[h] * A_h) @ h2   (ASUM in smem)

#define NLOC 1024
#define NNEI 128
#define NG2  32
#define NH   4

#define INV_SQRT_ND 0.17677669529663687f   // 1/sqrt(32)
#define INV_SQRT3   0.57735026918962576f   // 1/sqrt(3)
#define ATTNW_SHIFT 20.0f
#define SUM_SCALE   8388608.0f             // 2^23

typedef unsigned long long u64;

__device__ __forceinline__ u64 pk2(float lo, float hi) {
    u64 r;
    asm("mov.b64 %0, {%1, %2};" : "=l"(r) : "f"(lo), "f"(hi));
    return r;
}
__device__ __forceinline__ void upk2(u64 v, float& lo, float& hi) {
    asm("mov.b64 {%0, %1}, %2;" : "=f"(lo), "=f"(hi) : "l"(v));
}
__device__ __forceinline__ void fma2(u64& d, u64 a, u64 b) {
    asm("fma.rn.f32x2 %0, %1, %2, %0;" : "+l"(d) : "l"(a), "l"(b));
}
__device__ __forceinline__ float hsum2(u64 v) {
    float lo, hi; upk2(v, lo, hi); return lo + hi;
}
// Warp-wide f32 max via s32 redux on the monotone float<->int map (exact).
__device__ __forceinline__ float warp_max_f32(float v) {
    int iv = __float_as_int(v);
    iv = (iv >= 0) ? iv : (iv ^ 0x7fffffff);
    int r;
    asm("redux.sync.max.s32 %0, %1, 0xffffffff;" : "=r"(r) : "r"(iv));
    r = (r >= 0) ? r : (r ^ 0x7fffffff);
    return __int_as_float(r);
}
// Warp-wide sum of non-negative bounded floats via fixed-point s32 redux.
// Returns the sum SCALED by 2^23 (caller folds 2^23 into its reciprocal).
__device__ __forceinline__ float warp_sum_scaled_f32(float v) {
    int iv = __float2int_rn(v * SUM_SCALE);
    int r;
    asm("redux.sync.add.s32 %0, %1, 0xffffffff;" : "=r"(r) : "r"(iv));
    return __int2float_rn(r);
}

// Precomputed W2[h][j][o] = sum_g w_v[j, g*4+h] * w_head[g*4+h, o]
// Precomputed M[h][j][jp] = (1/sqrt(nd)) * sum_d w_qk[j, d*8+h] * w_qk[jp, d*8+4+h]
__device__ float g_W2[NH][NG2][NG2];
__device__ float g_M[NH][NG2][NG2];

__global__ void precompute_kernel(const float* __restrict__ w_v,
                                  const float* __restrict__ w_head,
                                  const float* __restrict__ w_qk) {
    int t = blockIdx.x * blockDim.x + threadIdx.x;   // 8192 outputs
    if (t >= 2 * NH * NG2 * NG2) return;
    int o = t & 31;
    int j = (t >> 5) & 31;
    int h = (t >> 10) & 3;
    if (t < NH * NG2 * NG2) {
        float s = 0.0f;
#pragma unroll
        for (int g = 0; g < 32; g++)
            s = fmaf(w_v[j * 128 + g * 4 + h], w_head[(g * 4 + h) * 32 + o], s);
        g_W2[h][j][o] = s;
    } else {
        float s = 0.0f;
#pragma unroll
        for (int d = 0; d < 32; d++)
            s = fmaf(w_qk[j * 256 + d * 8 + h], w_qk[o * 256 + d * 8 + 4 + h], s);
        g_M[h][j][o] = s * INV_SQRT_ND;
    }
}

// ---- shared memory layout (floats) ----
// G2P  [128][36]    : 0      .. 4608    (pad 36: conflict-free .128 row reads)
// QS   [128][36]    : 4608   .. 9216
// PS   [32][4][40]  : 9216   .. 14336   (PS[k][o] at (k%32)*160 + (k/32)*40 + o)
// AS   [128][144]   : 14336  .. 32768   (A[q][k] at q*144 + (k/32)*36 + (k%32))
// ASUM [128][132]   : 32768  .. 49664
// H2S  [128][5]     : 49664  .. 50304
// SWS  [128]        : 50304  .. 50432
// MFS  [128]        : 50432  .. 50560
#define SM_FLOATS 50560

__global__ __launch_bounds__(512, 1)
void repformer_kernel(const float* __restrict__ g2,
                      const float* __restrict__ h2,
                      const float* __restrict__ sw,
                      const float* __restrict__ b_head,
                      const float* __restrict__ w_eqhead,
                      const int*   __restrict__ nlist_mask,
                      float* __restrict__ out) {
    extern __shared__ float sm[];
    float* G2P  = sm;
    float* QS   = sm + 4608;
    float* PS   = sm + 9216;
    float* AS   = sm + 14336;
    float* ASUM = sm + 32768;
    float* H2S  = sm + 49664;
    float* SWS  = sm + 50304;
    float* MFS  = sm + 50432;

    const int i    = blockIdx.x;
    const int tid  = threadIdx.x;
    const int lane = tid & 31;
    const int w    = tid >> 5;   // warp 0..15
    const int g    = lane >> 3;  // phase-c k-quarter group
    const int s    = lane & 7;

    // ---- load tile ----
    {
        const float4* src = (const float4*)(g2 + (size_t)i * NNEI * NG2);
        for (int v = tid; v < NNEI * NG2 / 4; v += 512) {
            int n  = v >> 3;
            int j4 = v & 7;
            *(float4*)(G2P + n * 36 + j4 * 4) = src[v];
        }
        if (tid < NNEI) {
            int n = tid;
            size_t base = ((size_t)i * NNEI + n);
            H2S[n * 5 + 0] = h2[base * 3 + 0];
            H2S[n * 5 + 1] = h2[base * 3 + 1];
            H2S[n * 5 + 2] = h2[base * 3 + 2];
            SWS[n] = sw[base];
            MFS[n] = nlist_mask[base] ? 1.0f : 0.0f;
        }
    }
    __syncthreads();

    // phase-c persistent accumulators: warp w owns rows w*8..+7;
    // lane (g,s) owns o in {s,s+8} (accO0) and {s+16,s+24} (accO1), k in [g*32, g*32+32)
    u64 accO0[8], accO1[8];
#pragma unroll
    for (int r = 0; r < 8; r++) { accO0[r] = 0ull; accO1[r] = 0ull; }

#pragma unroll 1
    for (int h = 0; h < NH; h++) {
        const float weq = w_eqhead[h];

        // ============ phase a: QS = g2 @ M_h,  PS = g2 @ W2_h ============
        // thread: column = lane, rows = w + 16*r (r=0..7). Packed weights + FFMA2.
#pragma unroll 1
        for (int m = 0; m < 2; m++) {
            u64 wreg[16];
            if (m == 0) {
#pragma unroll
                for (int t = 0; t < 16; t++)
                    wreg[t] = pk2(g_M[h][2 * t][lane], g_M[h][2 * t + 1][lane]);
            } else {
#pragma unroll
                for (int t = 0; t < 16; t++)
                    wreg[t] = pk2(g_W2[h][2 * t][lane], g_W2[h][2 * t + 1][lane]);
            }
            u64 acc[8];
#pragma unroll
            for (int r = 0; r < 8; r++) acc[r] = 0ull;
#pragma unroll
            for (int j4 = 0; j4 < 8; j4++) {
#pragma unroll
                for (int r = 0; r < 8; r++) {
                    ulonglong2 gv = *(const ulonglong2*)(G2P + (w + 16 * r) * 36 + j4 * 4);
                    fma2(acc[r], gv.x, wreg[2 * j4]);
                    fma2(acc[r], gv.y, wreg[2 * j4 + 1]);
                }
            }
            if (m == 0) {
#pragma unroll
                for (int r = 0; r < 8; r++)
                    QS[(w + 16 * r) * 36 + lane] = hsum2(acc[r]);
            } else {
#pragma unroll
                for (int r = 0; r < 8; r++) {
                    int row = w + 16 * r;
                    PS[(row & 31) * 160 + (row >> 5) * 40 + lane] = hsum2(acc[r]);
                }
            }
        }
        __syncthreads();

        // ============ phase b: S = T @ g2^T + scaling + softmax + masking ============
        // warp w owns rows w*8..w*8+7; lane owns k = lane + 32*m (K operand = G2P rows)
        {
            const int qbase = w * 8;

            float hk0[4], hk1[4], hk2[4], swk[4], kc[4];
#pragma unroll
            for (int m = 0; m < 4; m++) {
                int k = lane + 32 * m;
                hk0[m] = H2S[k * 5 + 0];
                hk1[m] = H2S[k * 5 + 1];
                hk2[m] = H2S[k * 5 + 2];
                swk[m] = SWS[k];
                kc[m]  = swk[m] * MFS[k];
            }

            // packed accumulators: pair 0 = (m0,m1), pair 1 = (m2,m3)
            u64 acc2[8][2];
#pragma unroll
            for (int r = 0; r < 8; r++) { acc2[r][0] = 0ull; acc2[r][1] = 0ull; }

#pragma unroll
            for (int d4 = 0; d4 < 8; d4++) {
                float4 kv[4];
#pragma unroll
                for (int m = 0; m < 4; m++)
                    kv[m] = *(const float4*)(G2P + (lane + 32 * m) * 36 + d4 * 4);
                u64 kp0x = pk2(kv[0].x, kv[1].x), kp1x = pk2(kv[2].x, kv[3].x);
                u64 kp0y = pk2(kv[0].y, kv[1].y), kp1y = pk2(kv[2].y, kv[3].y);
                u64 kp0z = pk2(kv[0].z, kv[1].z), kp1z = pk2(kv[2].z, kv[3].z);
                u64 kp0w = pk2(kv[0].w, kv[1].w), kp1w = pk2(kv[2].w, kv[3].w);
#pragma unroll
                for (int r = 0; r < 8; r++) {
                    float4 qv = *(const float4*)(QS + (qbase + r) * 36 + d4 * 4);
                    u64 qx = pk2(qv.x, qv.x);
                    u64 qy = pk2(qv.y, qv.y);
                    u64 qz = pk2(qv.z, qv.z);
                    u64 qw = pk2(qv.w, qv.w);
                    fma2(acc2[r][0], qx, kp0x); fma2(acc2[r][1], qx, kp1x);
                    fma2(acc2[r][0], qy, kp0y); fma2(acc2[r][1], qy, kp1y);
                    fma2(acc2[r][0], qz, kp0z); fma2(acc2[r][1], qz, kp1z);
                    fma2(acc2[r][0], qw, kp0w); fma2(acc2[r][1], qw, kp1w);
                }
            }

#pragma unroll
            for (int r = 0; r < 8; r++) {
                const int q = qbase + r;
                const float hq0 = H2S[q * 5 + 0];
                const float hq1 = H2S[q * 5 + 1];
                const float hq2 = H2S[q * 5 + 2];
                const float swq = SWS[q];
                const float mq  = MFS[q];

                float sc[4];
                upk2(acc2[r][0], sc[0], sc[1]);
                upk2(acc2[r][1], sc[2], sc[3]);

                float hh[4], val[4];
#pragma unroll
                for (int m = 0; m < 4; m++) {
                    hh[m] = fmaf(hq0, hk0[m], fmaf(hq1, hk1[m], hq2 * hk2[m]));
                    float a = sc[m] * hh[m];
                    val[m] = (a + ATTNW_SHIFT) * swq * swk[m] - ATTNW_SHIFT;
                }
                // row max: single REDUX via monotone float<->s32 map (exact)
                float mx = fmaxf(fmaxf(val[0], val[1]), fmaxf(val[2], val[3]));
                mx = warp_max_f32(mx);
                float ssum = 0.0f;
#pragma unroll
                for (int m = 0; m < 4; m++) {
                    val[m] = __expf(val[m] - mx);
                    ssum += val[m];
                }
                // row sum: fixed-point REDUX (returns sum * 2^23); fold 2^23 into rowc
                float ssum_scaled = warp_sum_scaled_f32(ssum);
                const float rowc = __frcp_rn(ssum_scaled) * (SUM_SCALE * INV_SQRT3) * swq * mq;

#pragma unroll
                for (int m = 0; m < 4; m++) {
                    float A = val[m] * rowc * kc[m] * hh[m];
                    // AS layout: q*144 + (k/32)*36 + (k%32), k = lane + 32m
                    AS[q * 144 + m * 36 + lane] = A;
                    int kk = lane + 32 * m;
                    if (h == 0) ASUM[q * 132 + kk] = weq * A;
                    else        ASUM[q * 132 + kk] += weq * A;
                }
            }
        }
        __syncwarp();   // AS warp-private: only STS->LDS visibility within warp needed

        // ============ phase c: accO += A[q][k-quarter] * P[k][o-set] (grouped gather) ======
        {
            const int rowbase = w * 8;
            const float* PSg = PS + g * 40;
#pragma unroll 2
            for (int k4 = 0; k4 < 8; k4++) {
                // P operands, row-invariant: k = g*32 + k4*4 + j
                u64 pP0[4], pP1[4];
#pragma unroll
                for (int j = 0; j < 4; j++) {
                    const float* prow = PSg + (k4 * 4 + j) * 160;
                    pP0[j] = pk2(prow[s],      prow[s + 8]);
                    pP1[j] = pk2(prow[s + 16], prow[s + 24]);
                }
#pragma unroll
                for (int r = 0; r < 8; r++) {
                    // one LDS.128 serves 4 groups' distinct 16B chunks
                    const float4 a = *(const float4*)(AS + (rowbase + r) * 144 + g * 36 + k4 * 4);
                    u64 a0 = pk2(a.x, a.x);
                    u64 a1 = pk2(a.y, a.y);
                    u64 a2 = pk2(a.z, a.z);
                    u64 a3 = pk2(a.w, a.w);
                    fma2(accO0[r], a0, pP0[0]); fma2(accO1[r], a0, pP1[0]);
                    fma2(accO0[r], a1, pP0[1]); fma2(accO1[r], a1, pP1[1]);
                    fma2(accO0[r], a2, pP0[2]); fma2(accO1[r], a2, pP1[2]);
                    fma2(accO0[r], a3, pP0[3]); fma2(accO1[r], a3, pP1[3]);
                }
            }
        }
        __syncthreads();   // QS/PS reused next head
    }

    // ---- epilogue: g2_out — bfly-reduce partials over k-quarter groups ----
    {
        const int rowbase = w * 8;
        const float bb0 = b_head[s];
        const float bb1 = b_head[s + 8];
        const float bb2 = b_head[s + 16];
        const float bb3 = b_head[s + 24];
#pragma unroll
        for (int r = 0; r < 8; r++) {
            float o0, o1, o2, o3;
            upk2(accO0[r], o0, o1);
            upk2(accO1[r], o2, o3);
#pragma unroll
            for (int sh = 8; sh <= 16; sh <<= 1) {
                o0 += __shfl_xor_sync(0xffffffffu, o0, sh);
                o1 += __shfl_xor_sync(0xffffffffu, o1, sh);
                o2 += __shfl_xor_sync(0xffffffffu, o2, sh);
                o3 += __shfl_xor_sync(0xffffffffu, o3, sh);
            }
            if (g == 0) {
                int q = rowbase + r;
                float* po = out + ((size_t)i * NNEI + q) * 32;
                po[s]      = o0 + bb0;
                po[s + 8]  = o1 + bb1;
                po[s + 16] = o2 + bb2;
                po[s + 24] = o3 + bb3;
            }
        }
    }

    // ---- epilogue: h2_out = ASUM @ h2 ----
    if (tid < 128) {
        const int q = tid;
        float s0 = 0.0f, s1 = 0.0f, s2 = 0.0f;
#pragma unroll 4
        for (int k4 = 0; k4 < 32; k4++) {
            float4 a = *(const float4*)(ASUM + q * 132 + k4 * 4);
            float av[4] = {a.x, a.y, a.z, a.w};
#pragma unroll
            for (int u = 0; u < 4; u++) {
                int k = k4 * 4 + u;
                s0 = fmaf(av[u], H2S[k * 5 + 0], s0);
                s1 = fmaf(av[u], H2S[k * 5 + 1], s1);
                s2 = fmaf(av[u], H2S[k * 5 + 2], s2);
            }
        }
        float* oh = out + (size_t)NLOC * NNEI * 32;
        size_t base = ((size_t)i * NNEI + q) * 3;
        oh[base + 0] = s0;
        oh[base + 1] = s1;
        oh[base + 2] = s2;
    }
}

extern "C" void kernel_launch(void* const* d_in, const int* in_sizes, int n_in,
                              void* d_out, int out_size) {
    const float* g2       = (const float*)d_in[0];
    const float* h2       = (const float*)d_in[1];
    const float* sw       = (const float*)d_in[2];
    const float* w_qk     = (const float*)d_in[3];
    const float* w_v      = (const float*)d_in[4];
    const float* w_head   = (const float*)d_in[5];
    const float* b_head   = (const float*)d_in[6];
    const float* w_eqhead = (const float*)d_in[7];
    const int*   nmask    = (const int*)d_in[8];
    float* out = (float*)d_out;

    precompute_kernel<<<32, 256>>>(w_v, w_head, w_qk);

    const size_t smem = (size_t)SM_FLOATS * sizeof(float);   // ~197.5 KB
    cudaFuncSetAttribute(repformer_kernel,
                         cudaFuncAttributeMaxDynamicSharedMemorySize, (int)smem);
    repformer_kernel<<<NLOC, 512, smem>>>(g2, h2, sw, b_head, w_eqhead, nmask, out);
}